// round 13
// baseline (speedup 1.0000x reference)
#include <cuda_runtime.h>

#define NN 2048
#define NE 65536
#define NVIEWS 6
#define C 32

typedef unsigned long long ull;

// ---- scratch. Invariant: g_agg == 0, g_cnt == 0 at entry of kernel_launch
// (zero-init at load; every consumer restores zeros). ----
__device__ float g_agg[NN * C];
__device__ int   g_cnt[NN];
__device__ float g_inv[NN];
__device__ float g_h1[NN * C];
__device__ float g_h2[NN * C];
__device__ float g_h3[NN * C];

// ---- f32x2 helpers ----
__device__ __forceinline__ ull pk(float lo, float hi) {
    ull r; asm("mov.b64 %0, {%1,%2};" : "=l"(r) : "f"(lo), "f"(hi)); return r;
}
__device__ __forceinline__ void upk(ull v, float& lo, float& hi) {
    asm("mov.b64 {%0,%1}, %2;" : "=f"(lo), "=f"(hi) : "l"(v));
}
__device__ __forceinline__ ull fma2(ull a, ull b, ull c) {
    ull d; asm("fma.rn.f32x2 %0,%1,%2,%3;" : "=l"(d) : "l"(a), "l"(b), "l"(c)); return d;
}
__device__ __forceinline__ ull add2(ull a, ull b) {
    ull d; asm("add.rn.f32x2 %0,%1,%2;" : "=l"(d) : "l"(a), "l"(b)); return d;
}

#define ABSMASK 0x7FFFFFFF7FFFFFFFULL

// ---- dummy first launch: keeps hot layer-3 edge_heavy at ncu capture index 5 ----
__global__ void warm_kernel() {}

// ---- layer 1 edge: in_c = 1. One warp per edge. Also counts degree. ----
__global__ void edge1_kernel(const float* __restrict__ x,
                             const int* __restrict__ ei,
                             const float* __restrict__ ea,
                             const float* __restrict__ W1,
                             const float* __restrict__ b1) {
    int gid  = blockIdx.x * blockDim.x + threadIdx.x;
    int e    = gid >> 5;
    int lane = gid & 31;
    if (e >= NE) return;
    float aval = (lane < NVIEWS) ? ea[e * NVIEWS + lane] : 0.f;
    int src = ei[e];
    int dst = ei[NE + e];
    float xs = __ldg(&x[src]);
    float wr = __ldg(&b1[lane]);
#pragma unroll
    for (int v = 0; v < NVIEWS; v++)
        wr = fmaf(__shfl_sync(0xffffffffu, aval, v), __ldg(&W1[v * C + lane]), wr);
    atomicAdd(&g_agg[dst * C + lane], xs * fmaxf(wr, 0.f));
    if (lane == 0) atomicAdd(&g_cnt[dst], 1);
}

// ---- node update 1 + stash inv + restore zeros ----
__global__ void node1_kernel(const float* __restrict__ x,
                             const float* __restrict__ root1,
                             const float* __restrict__ bias1) {
    int idx = blockIdx.x * blockDim.x + threadIdx.x;  // NN*C threads
    int n = idx >> 5, o = idx & 31;
    float inv = 1.f / fmaxf((float)g_cnt[n], 1.f);
    float v = fmaf(g_agg[idx], inv, fmaf(x[n], root1[o], bias1[o]));
    g_h1[idx] = fmaxf(v, 0.f);
    g_agg[idx] = 0.f;
    if (o == 0) { g_inv[n] = inv; g_cnt[n] = 0; }
}

// ---- heavy edge layer (in_c = 32). PERSISTENT: 296 blocks (2/SM), chunks
// of 64 edges. W/bias in smem ONCE per block as PLAIN f32 (32 KB, not the
// 56 KB dup layout): layout [ip][c4][o][4] so one float4 LDS.128 per lane
// gives 4 weights; (w,w) dup built in regs on the idle alu pipe. Halves
// smem crossbar bytes (R10: L1 55% was co-binding with fma 41%).
// 8 warps, TE=8 edges/warp (NP=4 pairs), lane = output channel.
// relu folded: (wr + |wr|) * (0.5*h), h pre-scaled. ----
#define TE 8
#define NP 4
#define EH_GRID 296
#define EH_CHUNKS (NE / (8 * TE))   // 1024 chunks of 64 edges
// Wf f32 layout: c = 0..15 per ip (2 i-channels): c=2v -> W[v][2ip][o],
// c=2v+1 -> W[v][2ip+1][o] (v=0..5); c=12/13 -> bias[2ip]/[2ip+1]; 14,15 pad.
// f32 index = ip*512 + (c>>2)*128 + o*4 + (c&3).
__global__ __launch_bounds__(256, 2)
void edge_heavy_kernel(int hin_sel,
                       const int* __restrict__ ei,
                       const float* __restrict__ ea,
                       const float* __restrict__ W,
                       const float* __restrict__ b) {
    __shared__ __align__(16) float Wf[16 * 16 * 32];   // 32 KB
    __shared__ __align__(16) ull hpp[8 * NP * 32];     // 8 KB
    for (int idx = threadIdx.x; idx < 16 * 16 * 32; idx += 256) {
        int k  = idx & 3;
        int o  = (idx >> 2) & 31;
        int c4 = (idx >> 7) & 3;
        int ip = idx >> 9;
        int c  = c4 * 4 + k;
        int i  = 2 * ip + (c & 1);
        float val = 0.f;
        if (c < 12)      val = W[(c >> 1) * 1024 + i * 32 + o];
        else if (c < 14) val = b[i * 32 + o];
        Wf[idx] = val;
    }
    __syncthreads();

    const float* __restrict__ h = (hin_sel == 1) ? g_h1 : g_h2;
    const float4* __restrict__ W4 = (const float4*)Wf;

    int lane = threadIdx.x & 31;
    int w    = threadIdx.x >> 5;

    for (int chunk = blockIdx.x; chunk < EH_CHUNKS; chunk += EH_GRID) {
        int base = (chunk * 8 + w) * TE;

        // 48 contiguous edge_attr floats for 8 edges
        float av0 = ea[base * NVIEWS + lane];
        float av1 = (lane < 16) ? ea[base * NVIEWS + 32 + lane] : 0.f;

        ull a2[NP][NVIEWS];
#pragma unroll
        for (int p = 0; p < NP; p++)
#pragma unroll
            for (int v = 0; v < NVIEWS; v++) {
                const int f0 = (2 * p) * NVIEWS + v;
                const int f1 = f0 + NVIEWS;
                float x0 = (f0 < 32) ? __shfl_sync(0xffffffffu, av0, f0)
                                     : __shfl_sync(0xffffffffu, av1, f0 - 32);
                float x1 = (f1 < 32) ? __shfl_sync(0xffffffffu, av0, f1)
                                     : __shfl_sync(0xffffffffu, av1, f1 - 32);
                a2[p][v] = pk(x0, x1);
            }

        int srci = 0, dsti = 0;
        if (lane < TE) {
            srci = ei[base + lane];
            dsti = ei[NE + base + lane];
        }

        // gather h rows (pre-scaled by 0.5) for the 8 source nodes
#pragma unroll
        for (int p = 0; p < NP; p++) {
            int s0 = __shfl_sync(0xffffffffu, srci, 2 * p);
            int s1 = __shfl_sync(0xffffffffu, srci, 2 * p + 1);
            hpp[(w * NP + p) * 32 + lane] =
                pk(0.5f * h[s0 * C + lane], 0.5f * h[s1 * C + lane]);
        }
        __syncwarp();

        ull acc2[NP];
#pragma unroll
        for (int p = 0; p < NP; p++) acc2[p] = 0ull;

#pragma unroll 2
        for (int ip = 0; ip < 16; ip++) {
            // 4 LDS.128: 16 plain f32 weights for 2 i-channels
            float4 q0 = W4[(ip * 4 + 0) * 32 + lane];  // W0[i] W0[i'] W1[i] W1[i']
            float4 q1 = W4[(ip * 4 + 1) * 32 + lane];  // W2[i] W2[i'] W3[i] W3[i']
            float4 q2 = W4[(ip * 4 + 2) * 32 + lane];  // W4[i] W4[i'] W5[i] W5[i']
            float4 q3 = W4[(ip * 4 + 3) * 32 + lane];  // b[i]  b[i']  pad   pad
            // dup on alu pipe (idle at 14%)
            ull wv0A = pk(q0.x, q0.x), wv0B = pk(q0.y, q0.y);
            ull wv1A = pk(q0.z, q0.z), wv1B = pk(q0.w, q0.w);
            ull wv2A = pk(q1.x, q1.x), wv2B = pk(q1.y, q1.y);
            ull wv3A = pk(q1.z, q1.z), wv3B = pk(q1.w, q1.w);
            ull wv4A = pk(q2.x, q2.x), wv4B = pk(q2.y, q2.y);
            ull wv5A = pk(q2.z, q2.z), wv5B = pk(q2.w, q2.w);
            ull wbA  = pk(q3.x, q3.x), wbB  = pk(q3.y, q3.y);
#pragma unroll
            for (int p = 0; p < NP; p++) {
                ulonglong2 hh = *(const ulonglong2*)&hpp[(w * NP + p) * 32 + (ip << 1)];
                ull wrA = wbA;
                wrA = fma2(a2[p][0], wv0A, wrA);
                wrA = fma2(a2[p][1], wv1A, wrA);
                wrA = fma2(a2[p][2], wv2A, wrA);
                wrA = fma2(a2[p][3], wv3A, wrA);
                wrA = fma2(a2[p][4], wv4A, wrA);
                wrA = fma2(a2[p][5], wv5A, wrA);
                ull wrB = wbB;
                wrB = fma2(a2[p][0], wv0B, wrB);
                wrB = fma2(a2[p][1], wv1B, wrB);
                wrB = fma2(a2[p][2], wv2B, wrB);
                wrB = fma2(a2[p][3], wv3B, wrB);
                wrB = fma2(a2[p][4], wv4B, wrB);
                wrB = fma2(a2[p][5], wv5B, wrB);
                // relu folded: (wr + |wr|) * (0.5*h)
                acc2[p] = fma2(hh.x, add2(wrA, wrA & ABSMASK), acc2[p]);
                acc2[p] = fma2(hh.y, add2(wrB, wrB & ABSMASK), acc2[p]);
            }
        }

#pragma unroll
        for (int p = 0; p < NP; p++) {
            int d0 = __shfl_sync(0xffffffffu, dsti, 2 * p);
            int d1 = __shfl_sync(0xffffffffu, dsti, 2 * p + 1);
            float lo, hi; upk(acc2[p], lo, hi);
            atomicAdd(&g_agg[d0 * C + lane], lo);
            atomicAdd(&g_agg[d1 * C + lane], hi);
        }
        __syncwarp();
    }
}

// ---- node update 2/3: warp per node, root via L1 (no smem/sync). ----
__global__ void nodeM_kernel(int sel,
                             const float* __restrict__ root,
                             const float* __restrict__ bias) {
    const float* __restrict__ hin = (sel == 1) ? g_h1 : g_h2;
    float* __restrict__ hout      = (sel == 1) ? g_h2 : g_h3;

    int warp = (blockIdx.x * blockDim.x + threadIdx.x) >> 5;
    int lane = threadIdx.x & 31;
    if (warp >= NN) return;
    int idx = warp * C + lane;
    float hval = hin[idx];
    float acc  = fmaf(g_agg[idx], g_inv[warp], __ldg(&bias[lane]));
    g_agg[idx] = 0.f;
#pragma unroll
    for (int i = 0; i < C; i++)
        acc = fmaf(__shfl_sync(0xffffffffu, hval, i),
                   __ldg(&root[(i << 5) + lane]), acc);
    hout[idx] = fmaxf(acc, 0.f);
}

// ---- CBT: all-pairs L1. Block tile 64(i) x 128(j); thread = 4i x 8j.
// smem row stride 34 ull (17 ulonglong2) -> LDS.128 loads 2 k's per instr. ----
__global__ __launch_bounds__(256)
void cbt_kernel(float* __restrict__ out) {
    __shared__ __align__(16) ull hiD[64 * 34];   // [i][k] (v,v)      17 KB
    __shared__ __align__(16) ull hjN[64 * 34];   // [jp][k] (-h0,-h1) 17 KB
    int tid = threadIdx.x, lane = tid & 31, wrow = tid >> 5;
    int i0 = blockIdx.y * 64, j0 = blockIdx.x * 128;

#pragma unroll
    for (int r = 0; r < 8; r++) {
        int n = wrow * 8 + r;
        float v = g_h3[(i0 + n) * C + lane];
        hiD[n * 34 + lane] = pk(v, v);
    }
    float* fj = (float*)hjN;
#pragma unroll
    for (int r = 0; r < 16; r++) {
        int n = wrow * 16 + r;            // 0..127
        float v = g_h3[(j0 + n) * C + lane];
        fj[2 * ((n >> 1) * 34 + lane) + (n & 1)] = -v;
    }
    __syncthreads();

    int tx = tid & 15;   // j base
    int ty = tid >> 4;   // i group
    ull acc2[4][4];
#pragma unroll
    for (int aa = 0; aa < 4; aa++)
#pragma unroll
        for (int jj = 0; jj < 4; jj++) acc2[aa][jj] = 0ull;

#pragma unroll 4
    for (int kp = 0; kp < 16; kp++) {
        ulonglong2 aj[4];
#pragma unroll
        for (int jj = 0; jj < 4; jj++)
            aj[jj] = *(const ulonglong2*)&hjN[(tx + 16 * jj) * 34 + 2 * kp];
#pragma unroll
        for (int aa = 0; aa < 4; aa++) {
            ulonglong2 ai = *(const ulonglong2*)&hiD[(ty * 4 + aa) * 34 + 2 * kp];
#pragma unroll
            for (int jj = 0; jj < 4; jj++) {
                ull d0 = add2(ai.x, aj[jj].x) & ABSMASK;
                acc2[aa][jj] = add2(acc2[aa][jj], d0);
                ull d1 = add2(ai.y, aj[jj].y) & ABSMASK;
                acc2[aa][jj] = add2(acc2[aa][jj], d1);
            }
        }
    }
#pragma unroll
    for (int aa = 0; aa < 4; aa++) {
        size_t row = (size_t)(i0 + ty * 4 + aa) * NN;
#pragma unroll
        for (int jj = 0; jj < 4; jj++) {
            float lo, hi; upk(acc2[aa][jj], lo, hi);
            *(float2*)&out[row + j0 + 2 * (tx + 16 * jj)] = make_float2(lo, hi);
        }
    }
}

extern "C" void kernel_launch(void* const* d_in, const int* in_sizes, int n_in,
                              void* d_out, int out_size) {
    const float* x     = (const float*)d_in[0];
    const float* ea    = (const float*)d_in[1];
    const int*   ei    = (const int*)d_in[2];
    const float* W1    = (const float*)d_in[3];
    const float* b1    = (const float*)d_in[4];
    const float* root1 = (const float*)d_in[5];
    const float* bias1 = (const float*)d_in[6];
    const float* W2    = (const float*)d_in[7];
    const float* b2    = (const float*)d_in[8];
    const float* root2 = (const float*)d_in[9];
    const float* bias2 = (const float*)d_in[10];
    const float* W3    = (const float*)d_in[11];
    const float* b3    = (const float*)d_in[12];
    const float* root3 = (const float*)d_in[13];
    const float* bias3 = (const float*)d_in[14];
    float* out = (float*)d_out;

    // idx 0 (keeps ncu -s 5 on layer-3 edge_heavy)
    warm_kernel<<<1, 32>>>();
    // idx 1,2
    edge1_kernel<<<(NE * 32) / 256, 256>>>(x, ei, ea, W1, b1);
    node1_kernel<<<(NN * C) / 256, 256>>>(x, root1, bias1);
    // layer 2: idx 3,4
    edge_heavy_kernel<<<EH_GRID, 256>>>(1, ei, ea, W2, b2);
    nodeM_kernel<<<(NN * 32) / 256, 256>>>(1, root2, bias2);
    // layer 3: idx 5 (ncu capture), 6
    edge_heavy_kernel<<<EH_GRID, 256>>>(2, ei, ea, W3, b3);
    nodeM_kernel<<<(NN * 32) / 256, 256>>>(2, root3, bias3);
    // CBT: idx 7
    cbt_kernel<<<dim3(NN / 128, NN / 64), 256>>>(out);
}

// round 14
// speedup vs baseline: 1.5786x; 1.5786x over previous
#include <cuda_runtime.h>

#define NN 2048
#define NE 65536
#define NVIEWS 6
#define C 32

typedef unsigned long long ull;

// ---- scratch. Invariant: g_agg == 0, g_cnt == 0 at entry of kernel_launch
// (zero-init at load; every consumer restores zeros). ----
__device__ float g_agg[NN * C];
__device__ int   g_cnt[NN];
__device__ float g_inv[NN];
__device__ float g_h1[NN * C];
__device__ float g_h2[NN * C];
__device__ float g_h3[NN * C];

// ---- f32x2 helpers ----
__device__ __forceinline__ ull pk(float lo, float hi) {
    ull r; asm("mov.b64 %0, {%1,%2};" : "=l"(r) : "f"(lo), "f"(hi)); return r;
}
__device__ __forceinline__ void upk(ull v, float& lo, float& hi) {
    asm("mov.b64 {%0,%1}, %2;" : "=f"(lo), "=f"(hi) : "l"(v));
}
__device__ __forceinline__ ull fma2(ull a, ull b, ull c) {
    ull d; asm("fma.rn.f32x2 %0,%1,%2,%3;" : "=l"(d) : "l"(a), "l"(b), "l"(c)); return d;
}
__device__ __forceinline__ ull add2(ull a, ull b) {
    ull d; asm("add.rn.f32x2 %0,%1,%2;" : "=l"(d) : "l"(a), "l"(b)); return d;
}

#define ABSMASK 0x7FFFFFFF7FFFFFFFULL

// ---- dummy first launch: keeps hot layer-3 edge_heavy at ncu capture index 5 ----
__global__ void warm_kernel() {}

// ---- layer 1 edge: in_c = 1. One warp per edge. Also counts degree. ----
__global__ void edge1_kernel(const float* __restrict__ x,
                             const int* __restrict__ ei,
                             const float* __restrict__ ea,
                             const float* __restrict__ W1,
                             const float* __restrict__ b1) {
    int gid  = blockIdx.x * blockDim.x + threadIdx.x;
    int e    = gid >> 5;
    int lane = gid & 31;
    if (e >= NE) return;
    float aval = (lane < NVIEWS) ? ea[e * NVIEWS + lane] : 0.f;
    int src = ei[e];
    int dst = ei[NE + e];
    float xs = __ldg(&x[src]);
    float wr = __ldg(&b1[lane]);
#pragma unroll
    for (int v = 0; v < NVIEWS; v++)
        wr = fmaf(__shfl_sync(0xffffffffu, aval, v), __ldg(&W1[v * C + lane]), wr);
    atomicAdd(&g_agg[dst * C + lane], xs * fmaxf(wr, 0.f));
    if (lane == 0) atomicAdd(&g_cnt[dst], 1);
}

// ---- node update 1 + stash inv + restore zeros ----
__global__ void node1_kernel(const float* __restrict__ x,
                             const float* __restrict__ root1,
                             const float* __restrict__ bias1) {
    int idx = blockIdx.x * blockDim.x + threadIdx.x;  // NN*C threads
    int n = idx >> 5, o = idx & 31;
    float inv = 1.f / fmaxf((float)g_cnt[n], 1.f);
    float v = fmaf(g_agg[idx], inv, fmaf(x[n], root1[o], bias1[o]));
    g_h1[idx] = fmaxf(v, 0.f);
    g_agg[idx] = 0.f;
    if (o == 0) { g_inv[n] = inv; g_cnt[n] = 0; }
}

// ---- heavy edge layer (in_c = 32). R10 structure (proven 36.5us/layer:
// TE=8, dup-W smem, LDS.128, 2 blocks/SM) + cross-chunk SOFTWARE PIPELINE:
// ei LDG for chunk k+1 issued before the inner loop; h-gather + ea for k+1
// issued MID-inner-loop (between ip 0-7 and 8-15) so ~650 issue slots cover
// each latency; packed h stored to hpp at the top of the next iteration
// (same-warp order makes a single buffer safe).
// relu folded: (wr + |wr|) * (0.5*h), h pre-scaled. ----
#define TE 8
#define NP 4
#define EH_GRID 296
#define EH_CHUNKS (NE / (8 * TE))   // 1024 chunks of 64 edges
#define WD_ULL (7 * 1024)
__global__ __launch_bounds__(256, 2)
void edge_heavy_kernel(int hin_sel,
                       const int* __restrict__ ei,
                       const float* __restrict__ ea,
                       const float* __restrict__ W,
                       const float* __restrict__ b) {
    __shared__ __align__(16) ull Wd[WD_ULL];       // 56 KB dup (w,w), 2 ch adjacent
    __shared__ __align__(16) ull hpp[8 * NP * 32]; // 8 KB
    for (int idx = threadIdx.x; idx < 6 * 1024; idx += 256) {
        int v = idx >> 10, rem = idx & 1023, i = rem >> 5, o = rem & 31;
        float w = W[idx];
        Wd[((((v << 4) + (i >> 1)) << 5) + o) * 2 + (i & 1)] = pk(w, w);
    }
    for (int idx = threadIdx.x; idx < 1024; idx += 256) {
        int i = idx >> 5, o = idx & 31;
        float w = b[idx];
        Wd[6144 + ((((i >> 1) << 5) + o) << 1) + (i & 1)] = pk(w, w);
    }
    __syncthreads();

    const float* __restrict__ h = (hin_sel == 1) ? g_h1 : g_h2;

    int lane = threadIdx.x & 31;
    int w    = threadIdx.x >> 5;

    // ---- pipeline prologue: chunk0's ei, h-gather, ea ----
    int chunk = blockIdx.x;
    int eiS = 0, eiD = 0;
    float h0R[NP], h1R[NP];
    float av0, av1;
    {
        int base = (chunk * 8 + w) * TE;
        if (lane < TE) { eiS = ei[base + lane]; eiD = ei[NE + base + lane]; }
#pragma unroll
        for (int p = 0; p < NP; p++) {
            int s0 = __shfl_sync(0xffffffffu, eiS, 2 * p);
            int s1 = __shfl_sync(0xffffffffu, eiS, 2 * p + 1);
            h0R[p] = h[s0 * C + lane];
            h1R[p] = h[s1 * C + lane];
        }
        av0 = ea[base * NVIEWS + lane];
        av1 = (lane < 16) ? ea[base * NVIEWS + 32 + lane] : 0.f;
    }

    while (chunk < EH_CHUNKS) {
        int nchunk = chunk + EH_GRID;
        bool hasNext = (nchunk < EH_CHUNKS);
        int nbase = (nchunk * 8 + w) * TE;

        // store this chunk's gathered h (pre-scaled 0.5) into warp smem
#pragma unroll
        for (int p = 0; p < NP; p++)
            hpp[(w * NP + p) * 32 + lane] = pk(0.5f * h0R[p], 0.5f * h1R[p]);
        __syncwarp();

        // pack this chunk's a2 from av regs
        ull a2[NP][NVIEWS];
#pragma unroll
        for (int p = 0; p < NP; p++)
#pragma unroll
            for (int v = 0; v < NVIEWS; v++) {
                const int f0 = (2 * p) * NVIEWS + v;
                const int f1 = f0 + NVIEWS;
                float x0 = (f0 < 32) ? __shfl_sync(0xffffffffu, av0, f0)
                                     : __shfl_sync(0xffffffffu, av1, f0 - 32);
                float x1 = (f1 < 32) ? __shfl_sync(0xffffffffu, av0, f1)
                                     : __shfl_sync(0xffffffffu, av1, f1 - 32);
                a2[p][v] = pk(x0, x1);
            }

        int dstiC = eiD;   // keep this chunk's dst before overwrite

        // issue NEXT chunk's ei load (latency covered by inner half 1)
        int neiS = 0, neiD = 0;
        if (hasNext && lane < TE) {
            neiS = ei[nbase + lane];
            neiD = ei[NE + nbase + lane];
        }

        ull acc2[NP];
#pragma unroll
        for (int p = 0; p < NP; p++) acc2[p] = 0ull;

        int l2 = lane << 1;
        // ---- inner half 1: ip 0..7 ----
#pragma unroll 1
        for (int ip = 0; ip < 8; ip++) {
            ulonglong2 wb  = *(const ulonglong2*)&Wd[6144 + (ip << 6) + l2];
            ulonglong2 wv0 = *(const ulonglong2*)&Wd[(((0 << 4) + ip) << 6) + l2];
            ulonglong2 wv1 = *(const ulonglong2*)&Wd[(((1 << 4) + ip) << 6) + l2];
            ulonglong2 wv2 = *(const ulonglong2*)&Wd[(((2 << 4) + ip) << 6) + l2];
            ulonglong2 wv3 = *(const ulonglong2*)&Wd[(((3 << 4) + ip) << 6) + l2];
            ulonglong2 wv4 = *(const ulonglong2*)&Wd[(((4 << 4) + ip) << 6) + l2];
            ulonglong2 wv5 = *(const ulonglong2*)&Wd[(((5 << 4) + ip) << 6) + l2];
#pragma unroll
            for (int p = 0; p < NP; p++) {
                ulonglong2 hh = *(const ulonglong2*)&hpp[(w * NP + p) * 32 + (ip << 1)];
                ull wrA = wb.x;
                wrA = fma2(a2[p][0], wv0.x, wrA);
                wrA = fma2(a2[p][1], wv1.x, wrA);
                wrA = fma2(a2[p][2], wv2.x, wrA);
                wrA = fma2(a2[p][3], wv3.x, wrA);
                wrA = fma2(a2[p][4], wv4.x, wrA);
                wrA = fma2(a2[p][5], wv5.x, wrA);
                ull wrB = wb.y;
                wrB = fma2(a2[p][0], wv0.y, wrB);
                wrB = fma2(a2[p][1], wv1.y, wrB);
                wrB = fma2(a2[p][2], wv2.y, wrB);
                wrB = fma2(a2[p][3], wv3.y, wrB);
                wrB = fma2(a2[p][4], wv4.y, wrB);
                wrB = fma2(a2[p][5], wv5.y, wrB);
                acc2[p] = fma2(hh.x, add2(wrA, wrA & ABSMASK), acc2[p]);
                acc2[p] = fma2(hh.y, add2(wrB, wrB & ABSMASK), acc2[p]);
            }
        }

        // ---- mid-loop prefetch: NEXT chunk's h-gather + ea ----
        if (hasNext) {
#pragma unroll
            for (int p = 0; p < NP; p++) {
                int s0 = __shfl_sync(0xffffffffu, neiS, 2 * p);
                int s1 = __shfl_sync(0xffffffffu, neiS, 2 * p + 1);
                h0R[p] = h[s0 * C + lane];
                h1R[p] = h[s1 * C + lane];
            }
            av0 = ea[nbase * NVIEWS + lane];
            av1 = (lane < 16) ? ea[nbase * NVIEWS + 32 + lane] : 0.f;
        }

        // ---- inner half 2: ip 8..15 (covers prefetch latency) ----
#pragma unroll 1
        for (int ip = 8; ip < 16; ip++) {
            ulonglong2 wb  = *(const ulonglong2*)&Wd[6144 + (ip << 6) + l2];
            ulonglong2 wv0 = *(const ulonglong2*)&Wd[(((0 << 4) + ip) << 6) + l2];
            ulonglong2 wv1 = *(const ulonglong2*)&Wd[(((1 << 4) + ip) << 6) + l2];
            ulonglong2 wv2 = *(const ulonglong2*)&Wd[(((2 << 4) + ip) << 6) + l2];
            ulonglong2 wv3 = *(const ulonglong2*)&Wd[(((3 << 4) + ip) << 6) + l2];
            ulonglong2 wv4 = *(const ulonglong2*)&Wd[(((4 << 4) + ip) << 6) + l2];
            ulonglong2 wv5 = *(const ulonglong2*)&Wd[(((5 << 4) + ip) << 6) + l2];
#pragma unroll
            for (int p = 0; p < NP; p++) {
                ulonglong2 hh = *(const ulonglong2*)&hpp[(w * NP + p) * 32 + (ip << 1)];
                ull wrA = wb.x;
                wrA = fma2(a2[p][0], wv0.x, wrA);
                wrA = fma2(a2[p][1], wv1.x, wrA);
                wrA = fma2(a2[p][2], wv2.x, wrA);
                wrA = fma2(a2[p][3], wv3.x, wrA);
                wrA = fma2(a2[p][4], wv4.x, wrA);
                wrA = fma2(a2[p][5], wv5.x, wrA);
                ull wrB = wb.y;
                wrB = fma2(a2[p][0], wv0.y, wrB);
                wrB = fma2(a2[p][1], wv1.y, wrB);
                wrB = fma2(a2[p][2], wv2.y, wrB);
                wrB = fma2(a2[p][3], wv3.y, wrB);
                wrB = fma2(a2[p][4], wv4.y, wrB);
                wrB = fma2(a2[p][5], wv5.y, wrB);
                acc2[p] = fma2(hh.x, add2(wrA, wrA & ABSMASK), acc2[p]);
                acc2[p] = fma2(hh.y, add2(wrB, wrB & ABSMASK), acc2[p]);
            }
        }

        // scatter this chunk
#pragma unroll
        for (int p = 0; p < NP; p++) {
            int d0 = __shfl_sync(0xffffffffu, dstiC, 2 * p);
            int d1 = __shfl_sync(0xffffffffu, dstiC, 2 * p + 1);
            float lo, hi; upk(acc2[p], lo, hi);
            atomicAdd(&g_agg[d0 * C + lane], lo);
            atomicAdd(&g_agg[d1 * C + lane], hi);
        }

        eiS = neiS; eiD = neiD;
        chunk = nchunk;
        __syncwarp();
    }
}

// ---- node update 2/3: warp per node, root via L1 (no smem/sync). ----
__global__ void nodeM_kernel(int sel,
                             const float* __restrict__ root,
                             const float* __restrict__ bias) {
    const float* __restrict__ hin = (sel == 1) ? g_h1 : g_h2;
    float* __restrict__ hout      = (sel == 1) ? g_h2 : g_h3;

    int warp = (blockIdx.x * blockDim.x + threadIdx.x) >> 5;
    int lane = threadIdx.x & 31;
    if (warp >= NN) return;
    int idx = warp * C + lane;
    float hval = hin[idx];
    float acc  = fmaf(g_agg[idx], g_inv[warp], __ldg(&bias[lane]));
    g_agg[idx] = 0.f;
#pragma unroll
    for (int i = 0; i < C; i++)
        acc = fmaf(__shfl_sync(0xffffffffu, hval, i),
                   __ldg(&root[(i << 5) + lane]), acc);
    hout[idx] = fmaxf(acc, 0.f);
}

// ---- CBT: all-pairs L1. Block tile 64(i) x 128(j); thread = 4i x 8j.
// smem row stride 34 ull (17 ulonglong2) -> LDS.128 loads 2 k's per instr. ----
__global__ __launch_bounds__(256)
void cbt_kernel(float* __restrict__ out) {
    __shared__ __align__(16) ull hiD[64 * 34];   // [i][k] (v,v)      17 KB
    __shared__ __align__(16) ull hjN[64 * 34];   // [jp][k] (-h0,-h1) 17 KB
    int tid = threadIdx.x, lane = tid & 31, wrow = tid >> 5;
    int i0 = blockIdx.y * 64, j0 = blockIdx.x * 128;

#pragma unroll
    for (int r = 0; r < 8; r++) {
        int n = wrow * 8 + r;
        float v = g_h3[(i0 + n) * C + lane];
        hiD[n * 34 + lane] = pk(v, v);
    }
    float* fj = (float*)hjN;
#pragma unroll
    for (int r = 0; r < 16; r++) {
        int n = wrow * 16 + r;            // 0..127
        float v = g_h3[(j0 + n) * C + lane];
        fj[2 * ((n >> 1) * 34 + lane) + (n & 1)] = -v;
    }
    __syncthreads();

    int tx = tid & 15;   // j base
    int ty = tid >> 4;   // i group
    ull acc2[4][4];
#pragma unroll
    for (int aa = 0; aa < 4; aa++)
#pragma unroll
        for (int jj = 0; jj < 4; jj++) acc2[aa][jj] = 0ull;

#pragma unroll 4
    for (int kp = 0; kp < 16; kp++) {
        ulonglong2 aj[4];
#pragma unroll
        for (int jj = 0; jj < 4; jj++)
            aj[jj] = *(const ulonglong2*)&hjN[(tx + 16 * jj) * 34 + 2 * kp];
#pragma unroll
        for (int aa = 0; aa < 4; aa++) {
            ulonglong2 ai = *(const ulonglong2*)&hiD[(ty * 4 + aa) * 34 + 2 * kp];
#pragma unroll
            for (int jj = 0; jj < 4; jj++) {
                ull d0 = add2(ai.x, aj[jj].x) & ABSMASK;
                acc2[aa][jj] = add2(acc2[aa][jj], d0);
                ull d1 = add2(ai.y, aj[jj].y) & ABSMASK;
                acc2[aa][jj] = add2(acc2[aa][jj], d1);
            }
        }
    }
#pragma unroll
    for (int aa = 0; aa < 4; aa++) {
        size_t row = (size_t)(i0 + ty * 4 + aa) * NN;
#pragma unroll
        for (int jj = 0; jj < 4; jj++) {
            float lo, hi; upk(acc2[aa][jj], lo, hi);
            *(float2*)&out[row + j0 + 2 * (tx + 16 * jj)] = make_float2(lo, hi);
        }
    }
}

extern "C" void kernel_launch(void* const* d_in, const int* in_sizes, int n_in,
                              void* d_out, int out_size) {
    const float* x     = (const float*)d_in[0];
    const float* ea    = (const float*)d_in[1];
    const int*   ei    = (const int*)d_in[2];
    const float* W1    = (const float*)d_in[3];
    const float* b1    = (const float*)d_in[4];
    const float* root1 = (const float*)d_in[5];
    const float* bias1 = (const float*)d_in[6];
    const float* W2    = (const float*)d_in[7];
    const float* b2    = (const float*)d_in[8];
    const float* root2 = (const float*)d_in[9];
    const float* bias2 = (const float*)d_in[10];
    const float* W3    = (const float*)d_in[11];
    const float* b3    = (const float*)d_in[12];
    const float* root3 = (const float*)d_in[13];
    const float* bias3 = (const float*)d_in[14];
    float* out = (float*)d_out;

    // idx 0 (keeps ncu -s 5 on layer-3 edge_heavy)
    warm_kernel<<<1, 32>>>();
    // idx 1,2
    edge1_kernel<<<(NE * 32) / 256, 256>>>(x, ei, ea, W1, b1);
    node1_kernel<<<(NN * C) / 256, 256>>>(x, root1, bias1);
    // layer 2: idx 3,4
    edge_heavy_kernel<<<EH_GRID, 256>>>(1, ei, ea, W2, b2);
    nodeM_kernel<<<(NN * 32) / 256, 256>>>(1, root2, bias2);
    // layer 3: idx 5 (ncu capture), 6
    edge_heavy_kernel<<<EH_GRID, 256>>>(2, ei, ea, W3, b3);
    nodeM_kernel<<<(NN * 32) / 256, 256>>>(2, root3, bias3);
    // CBT: idx 7
    cbt_kernel<<<dim3(NN / 128, NN / 64), 256>>>(out);
}